// round 1
// baseline (speedup 1.0000x reference)
#include <cuda_runtime.h>

// Problem constants
#define BB     4
#define NQ     1024
#define NK     2048
#define DIMT   1024
#define NH     16
#define DH     64
#define ROWS_Q (BB*NQ)                  // 4096
#define ROWS_K (BB*NK)                  // 8192
#define ROWS_TOT (ROWS_Q + 2*ROWS_K)    // 20480

// Scratch (static device arrays: allocation-free per harness rules)
__device__ float g_ln[(size_t)ROWS_TOT * DIMT];   // LayerNorm'd q|k|v rows
__device__ float g_f [(size_t)ROWS_TOT * DIMT];   // projected features
__device__ float g_S [BB*NH*DH*DH];               // per-(b,h) 64x64  k_hat^T @ f_v
__device__ float g_attn[(size_t)ROWS_Q * DIMT];   // q_hat @ S, merged heads

// ---------------------------------------------------------------------------
// Kernel 1: LayerNorm all q/k/v rows into one contiguous buffer.
// One CTA per row (1024 elems), 256 threads, float4 per thread.
// ---------------------------------------------------------------------------
__global__ void __launch_bounds__(256) ln_kernel(
    const float* __restrict__ q, const float* __restrict__ k,
    const float* __restrict__ v, const float* __restrict__ gamma,
    const float* __restrict__ beta)
{
    int row = blockIdx.x;
    const float* src;
    if (row < ROWS_Q)               src = q + (size_t)row * DIMT;
    else if (row < ROWS_Q + ROWS_K) src = k + (size_t)(row - ROWS_Q) * DIMT;
    else                            src = v + (size_t)(row - ROWS_Q - ROWS_K) * DIMT;
    float* dst = g_ln + (size_t)row * DIMT;

    int t = threadIdx.x;
    float4 x = reinterpret_cast<const float4*>(src)[t];
    float s  = x.x + x.y + x.z + x.w;
    float ss = x.x*x.x + x.y*x.y + x.z*x.z + x.w*x.w;
    #pragma unroll
    for (int o = 16; o > 0; o >>= 1) {
        s  += __shfl_xor_sync(0xffffffffu, s,  o);
        ss += __shfl_xor_sync(0xffffffffu, ss, o);
    }
    __shared__ float ws[8], wss[8];
    int wid = t >> 5, lane = t & 31;
    if (lane == 0) { ws[wid] = s; wss[wid] = ss; }
    __syncthreads();
    float tot = 0.f, totss = 0.f;
    #pragma unroll
    for (int i = 0; i < 8; i++) { tot += ws[i]; totss += wss[i]; }
    float mu  = tot * (1.0f / DIMT);
    float var = totss * (1.0f / DIMT) - mu * mu;       // biased, matches ref
    float rs  = rsqrtf(var + 1e-5f);

    float4 g  = reinterpret_cast<const float4*>(gamma)[t];
    float4 be = reinterpret_cast<const float4*>(beta)[t];
    float4 y;
    y.x = (x.x - mu) * rs * g.x + be.x;
    y.y = (x.y - mu) * rs * g.y + be.y;
    y.z = (x.z - mu) * rs * g.z + be.z;
    y.w = (x.w - mu) * rs * g.w + be.w;
    reinterpret_cast<float4*>(dst)[t] = y;
}

// ---------------------------------------------------------------------------
// Kernel 2: SGEMM  C[M,N] = A[M,K] @ B[K,N] (+ bias[N]).
// 128x128 tile, BK=8, 256 threads, 8x8 per thread, float4 everywhere.
// M,N multiples of 128; K multiple of 8 (true for all uses here).
// ---------------------------------------------------------------------------
__global__ void __launch_bounds__(256, 2) sgemm128(
    const float* __restrict__ A, const float* __restrict__ Bm,
    float* __restrict__ C, int M, int N, int K,
    const float* __restrict__ bias)
{
    __shared__ float As[8][128];
    __shared__ float Bs[8][128];
    const int t    = threadIdx.x;
    const int brow = blockIdx.y, bcol = blockIdx.x;
    const int trow = t >> 4, tcol = t & 15;

    float acc[8][8];
    #pragma unroll
    for (int i = 0; i < 8; i++)
        #pragma unroll
        for (int j = 0; j < 8; j++) acc[i][j] = 0.f;

    const int aRow = t >> 1;
    const int aCol = (t & 1) << 2;
    const int bRow = t >> 5;
    const int bCol = (t & 31) << 2;
    const float* Ap = A  + (size_t)(brow * 128 + aRow) * K + aCol;
    const float* Bp = Bm + (size_t)bRow * N + bcol * 128 + bCol;

    for (int k0 = 0; k0 < K; k0 += 8) {
        float4 a4 = *reinterpret_cast<const float4*>(Ap + k0);
        As[aCol + 0][aRow] = a4.x;
        As[aCol + 1][aRow] = a4.y;
        As[aCol + 2][aRow] = a4.z;
        As[aCol + 3][aRow] = a4.w;
        *reinterpret_cast<float4*>(&Bs[bRow][bCol]) =
            *reinterpret_cast<const float4*>(Bp + (size_t)k0 * N);
        __syncthreads();
        #pragma unroll
        for (int kk = 0; kk < 8; kk++) {
            float ar[8], br[8];
            *reinterpret_cast<float4*>(&ar[0]) = *reinterpret_cast<float4*>(&As[kk][trow * 8]);
            *reinterpret_cast<float4*>(&ar[4]) = *reinterpret_cast<float4*>(&As[kk][trow * 8 + 4]);
            *reinterpret_cast<float4*>(&br[0]) = *reinterpret_cast<float4*>(&Bs[kk][tcol * 8]);
            *reinterpret_cast<float4*>(&br[4]) = *reinterpret_cast<float4*>(&Bs[kk][tcol * 8 + 4]);
            #pragma unroll
            for (int i = 0; i < 8; i++)
                #pragma unroll
                for (int j = 0; j < 8; j++)
                    acc[i][j] = fmaf(ar[i], br[j], acc[i][j]);
        }
        __syncthreads();
    }

    float bv[8];
    #pragma unroll
    for (int j = 0; j < 8; j++)
        bv[j] = bias ? bias[bcol * 128 + tcol * 8 + j] : 0.f;

    #pragma unroll
    for (int i = 0; i < 8; i++) {
        int row = brow * 128 + trow * 8 + i;
        float* Crow = C + (size_t)row * N + bcol * 128 + tcol * 8;
        float4 o0 = make_float4(acc[i][0] + bv[0], acc[i][1] + bv[1],
                                acc[i][2] + bv[2], acc[i][3] + bv[3]);
        float4 o1 = make_float4(acc[i][4] + bv[4], acc[i][5] + bv[5],
                                acc[i][6] + bv[6], acc[i][7] + bv[7]);
        *reinterpret_cast<float4*>(Crow)     = o0;
        *reinterpret_cast<float4*>(Crow + 4) = o1;
    }
}

// ---------------------------------------------------------------------------
// Kernel 3: per (b,h):  S = k_hat^T @ f_v   (64x64), summing over m=2048.
// One CTA per (b,h); 32-row tiles in shared; k row norms folded in.
// ---------------------------------------------------------------------------
__global__ void __launch_bounds__(256) kv_kernel()
{
    const int bh = blockIdx.x;
    const int b = bh >> 4, h = bh & 15;
    __shared__ float sk[32][64];
    __shared__ float sv[32][64];
    __shared__ float rkn[32];
    const int t = threadIdx.x;
    const int j1_0 = (t >> 4) << 2;
    const int j2_0 = (t & 15) << 2;
    const float* fk = g_f + (size_t)(ROWS_Q + b * NK) * DIMT + h * DH;
    const float* fv = g_f + (size_t)(ROWS_Q + ROWS_K + b * NK) * DIMT + h * DH;

    float acc[4][4];
    #pragma unroll
    for (int i = 0; i < 4; i++)
        #pragma unroll
        for (int j = 0; j < 4; j++) acc[i][j] = 0.f;

    for (int m0 = 0; m0 < NK; m0 += 32) {
        #pragma unroll
        for (int l = 0; l < 2; l++) {
            int idx = t + l * 256;               // 512 float4s per tensor
            int r = idx >> 4, c = (idx & 15) << 2;
            float4 kv4 = *reinterpret_cast<const float4*>(&fk[(size_t)(m0 + r) * DIMT + c]);
            float4 vv4 = *reinterpret_cast<const float4*>(&fv[(size_t)(m0 + r) * DIMT + c]);
            *reinterpret_cast<float4*>(&sk[r][c]) = kv4;
            *reinterpret_cast<float4*>(&sv[r][c]) = vv4;
            // fold k-row norm: 16 consecutive lanes own one row's 16 float4s
            float s = kv4.x*kv4.x + kv4.y*kv4.y + kv4.z*kv4.z + kv4.w*kv4.w;
            #pragma unroll
            for (int o = 8; o > 0; o >>= 1) s += __shfl_xor_sync(0xffffffffu, s, o);
            if ((t & 15) == 0) rkn[r] = rsqrtf(s);
        }
        __syncthreads();
        #pragma unroll 8
        for (int m = 0; m < 32; m++) {
            float rk = rkn[m];
            float4 a  = *reinterpret_cast<float4*>(&sk[m][j1_0]);
            float4 bq = *reinterpret_cast<float4*>(&sv[m][j2_0]);
            float a0 = a.x * rk, a1 = a.y * rk, a2 = a.z * rk, a3 = a.w * rk;
            acc[0][0] = fmaf(a0, bq.x, acc[0][0]); acc[0][1] = fmaf(a0, bq.y, acc[0][1]);
            acc[0][2] = fmaf(a0, bq.z, acc[0][2]); acc[0][3] = fmaf(a0, bq.w, acc[0][3]);
            acc[1][0] = fmaf(a1, bq.x, acc[1][0]); acc[1][1] = fmaf(a1, bq.y, acc[1][1]);
            acc[1][2] = fmaf(a1, bq.z, acc[1][2]); acc[1][3] = fmaf(a1, bq.w, acc[1][3]);
            acc[2][0] = fmaf(a2, bq.x, acc[2][0]); acc[2][1] = fmaf(a2, bq.y, acc[2][1]);
            acc[2][2] = fmaf(a2, bq.z, acc[2][2]); acc[2][3] = fmaf(a2, bq.w, acc[2][3]);
            acc[3][0] = fmaf(a3, bq.x, acc[3][0]); acc[3][1] = fmaf(a3, bq.y, acc[3][1]);
            acc[3][2] = fmaf(a3, bq.z, acc[3][2]); acc[3][3] = fmaf(a3, bq.w, acc[3][3]);
        }
        __syncthreads();
    }
    float* Sp = g_S + (size_t)bh * (DH * DH);
    #pragma unroll
    for (int i = 0; i < 4; i++)
        *reinterpret_cast<float4*>(&Sp[(j1_0 + i) * DH + j2_0]) =
            make_float4(acc[i][0], acc[i][1], acc[i][2], acc[i][3]);
}

// ---------------------------------------------------------------------------
// Kernel 4: out_attn[row, h*64+j2] = (f_q_row/|f_q_row|) @ S[b,h]
// CTA = (n-tile of 64 rows, bh). Q tile transposed into smem for vector reads.
// ---------------------------------------------------------------------------
__global__ void __launch_bounds__(256) qs_kernel()
{
    const int bh = blockIdx.y;
    const int nt = blockIdx.x;            // 16 tiles of 64 rows
    const int b = bh >> 4, h = bh & 15;
    __shared__ float sS[64][64];
    __shared__ float sqT[64][64];         // [j1][row]
    __shared__ float rqn[64];
    const int t = threadIdx.x;

    const float* Sp = g_S + (size_t)bh * (DH * DH);
    #pragma unroll
    for (int l = 0; l < 4; l++) {
        int idx = t + l * 256;
        reinterpret_cast<float4*>(sS)[idx] = reinterpret_cast<const float4*>(Sp)[idx];
    }
    const float* fq = g_f + (size_t)(b * NQ + nt * 64) * DIMT + h * DH;
    #pragma unroll
    for (int l = 0; l < 4; l++) {
        int idx = t + l * 256;
        int r = idx >> 4, c = (idx & 15) << 2;
        float4 x = *reinterpret_cast<const float4*>(&fq[(size_t)r * DIMT + c]);
        sqT[c + 0][r] = x.x; sqT[c + 1][r] = x.y;
        sqT[c + 2][r] = x.z; sqT[c + 3][r] = x.w;
        float s = x.x*x.x + x.y*x.y + x.z*x.z + x.w*x.w;
        #pragma unroll
        for (int o = 8; o > 0; o >>= 1) s += __shfl_xor_sync(0xffffffffu, s, o);
        if ((t & 15) == 0) rqn[r] = rsqrtf(s);
    }
    __syncthreads();

    float acc[4][4];
    #pragma unroll
    for (int i = 0; i < 4; i++)
        #pragma unroll
        for (int j = 0; j < 4; j++) acc[i][j] = 0.f;
    const int r0 = (t >> 4) << 2, c0 = (t & 15) << 2;
    #pragma unroll 8
    for (int j1 = 0; j1 < 64; j1++) {
        float4 a  = *reinterpret_cast<float4*>(&sqT[j1][r0]);
        float4 bq = *reinterpret_cast<float4*>(&sS[j1][c0]);
        acc[0][0] = fmaf(a.x, bq.x, acc[0][0]); acc[0][1] = fmaf(a.x, bq.y, acc[0][1]);
        acc[0][2] = fmaf(a.x, bq.z, acc[0][2]); acc[0][3] = fmaf(a.x, bq.w, acc[0][3]);
        acc[1][0] = fmaf(a.y, bq.x, acc[1][0]); acc[1][1] = fmaf(a.y, bq.y, acc[1][1]);
        acc[1][2] = fmaf(a.y, bq.z, acc[1][2]); acc[1][3] = fmaf(a.y, bq.w, acc[1][3]);
        acc[2][0] = fmaf(a.z, bq.x, acc[2][0]); acc[2][1] = fmaf(a.z, bq.y, acc[2][1]);
        acc[2][2] = fmaf(a.z, bq.z, acc[2][2]); acc[2][3] = fmaf(a.z, bq.w, acc[2][3]);
        acc[3][0] = fmaf(a.w, bq.x, acc[3][0]); acc[3][1] = fmaf(a.w, bq.y, acc[3][1]);
        acc[3][2] = fmaf(a.w, bq.z, acc[3][2]); acc[3][3] = fmaf(a.w, bq.w, acc[3][3]);
    }
    float* outp = g_attn + (size_t)(b * NQ + nt * 64 + r0) * DIMT + h * DH + c0;
    #pragma unroll
    for (int i = 0; i < 4; i++) {
        float rq = rqn[r0 + i];
        *reinterpret_cast<float4*>(outp + (size_t)i * DIMT) =
            make_float4(acc[i][0] * rq, acc[i][1] * rq, acc[i][2] * rq, acc[i][3] * rq);
    }
}

// ---------------------------------------------------------------------------
extern "C" void kernel_launch(void* const* d_in, const int* in_sizes, int n_in,
                              void* d_out, int out_size)
{
    const float* q     = (const float*)d_in[0];
    const float* k     = (const float*)d_in[1];
    const float* v     = (const float*)d_in[2];
    const float* gamma = (const float*)d_in[3];
    const float* beta  = (const float*)d_in[4];
    const float* W_in  = (const float*)d_in[5];
    const float* W_out = (const float*)d_in[6];
    const float* b_out = (const float*)d_in[7];
    float* out = (float*)d_out;

    float *p_ln, *p_f, *p_attn;
    cudaGetSymbolAddress((void**)&p_ln,   g_ln);
    cudaGetSymbolAddress((void**)&p_f,    g_f);
    cudaGetSymbolAddress((void**)&p_attn, g_attn);

    // 1) LayerNorm q|k|v
    ln_kernel<<<ROWS_TOT, 256>>>(q, k, v, gamma, beta);
    // 2) fused projection GEMM: f = LN(x) @ W_in   (20480 x 1024 x 1024)
    sgemm128<<<dim3(DIMT / 128, ROWS_TOT / 128), 256>>>(p_ln, W_in, p_f,
                                                        ROWS_TOT, DIMT, DIMT, nullptr);
    // 3) per-(b,h) S = k_hat^T @ f_v  (64x64 each)
    kv_kernel<<<BB * NH, 256>>>();
    // 4) attn_out = q_hat @ S, heads merged
    qs_kernel<<<dim3(NQ / 64, BB * NH), 256>>>();
    // 5) final GEMM + bias: out = attn_out @ W_out + b_out  (4096 x 1024 x 1024)
    sgemm128<<<dim3(DIMT / 128, ROWS_Q / 128), 256>>>(p_attn, W_out, out,
                                                      ROWS_Q, DIMT, DIMT, b_out);
}